// round 17
// baseline (speedup 1.0000x reference)
#include <cuda_runtime.h>
#include <cuda_fp16.h>
#include <math_constants.h>
#include <cstdint>

#define LL 768
#define HH 8
#define EE 64
#define NH 32
#define DD 192
#define BQ 64
#define NTILE 12
#define NITEMS 384          // 12 l-tiles x 32 nh
#define GRID_ATTN 360
#define KSTR 200            // f16 elems per K smem row (400B ≡ 16 mod 128 -> conflict-free)
#define VSTR 72             // f16 elems per V^T smem row

// ---------------- scratch (device globals; no allocs) ----------------
// d-layout: d = e for gate channel (0..63); d = 64+2e (cos), 65+2e (sin).
__device__ __half        g_Q[(size_t)NH * LL * DD];     // Q' fp16
__device__ __half        g_K[(size_t)NH * LL * DD];     // K' fp16
__device__ __half        g_V[(size_t)NH * EE * LL];     // V^T fp16 [nh][e][s]
__device__ unsigned int  g_ctr;

// m16n8k16 row.col fp16 MMA, f32 accumulate
__device__ __forceinline__ void mma_f16(float* c, const uint32_t* a, uint32_t b0, uint32_t b1) {
    asm volatile("mma.sync.aligned.m16n8k16.row.col.f32.f16.f16.f32 "
                 "{%0,%1,%2,%3}, {%4,%5,%6,%7}, {%8,%9}, {%0,%1,%2,%3};"
                 : "+f"(c[0]), "+f"(c[1]), "+f"(c[2]), "+f"(c[3])
                 : "r"(a[0]), "r"(a[1]), "r"(a[2]), "r"(a[3]), "r"(b0), "r"(b1));
}

__device__ __forceinline__ uint32_t smem_u32(const void* p) {
    uint32_t a;
    asm("{ .reg .u64 t; cvta.to.shared.u64 t, %1; cvt.u32.u64 %0, t; }" : "=r"(a) : "l"(p));
    return a;
}

#define CP16(dst, src) asm volatile("cp.async.cg.shared.global [%0], [%1], 16;" :: "r"(dst), "l"(src))
#define CP_COMMIT()    asm volatile("cp.async.commit_group;" ::: "memory")
#define CP_WAIT0()     asm volatile("cp.async.wait_group 0;" ::: "memory")

__device__ __forceinline__ uint32_t pack_h2(float x, float y) {
    __half2 h = __floats2half2_rn(x, y);
    return *(uint32_t*)&h;
}

// ---------------------------------------------------------------------------
// prep (fused): blockIdx.x < 48 -> Q'/K' fp16 build (e-pair threads, wide
// stores); else -> V transpose. Math identical to R16 (bit-exact outputs).
// ---------------------------------------------------------------------------
__global__ void prep_kernel(const float* __restrict__ q, const float* __restrict__ k,
                            const float* __restrict__ values,
                            const float* __restrict__ freqs, const float* __restrict__ offsets,
                            const float* __restrict__ gains, const float* __restrict__ gate) {
    const int nh = blockIdx.y;
    const int n = nh >> 3, h = nh & 7;

    if (blockIdx.x < 48) {
        if (blockIdx.x == 0 && blockIdx.y == 0 && threadIdx.x == 0)
            g_ctr = GRID_ATTN;                // seed attn work queue

        int ep = threadIdx.x & 31;            // e-pair index: e = 2ep, 2ep+1
        int j  = threadIdx.x >> 5;            // 0..7
        int l0 = blockIdx.x * 16 + j * 2;     // this thread: l0, l0+1
        int e0 = 2 * ep;

        const float TWO_PI = 6.28318530717958647692f;
        float f[2], off[2], cc[2], gt[2];
        float cq[2], sq[2], ck[2], sk[2], cF[2], sF[2];
        #pragma unroll
        for (int u = 0; u < 2; u++) {
            int he = h * 64 + e0 + u;
            float fr = freqs[he];
            f[u]   = 0.5f / (1.0f + __expf(-fr));
            off[u] = offsets[he];
            float gn = gains[he];
            float g  = (gn > 8.0f) ? gn : __logf(1.0f + __expf(gn));
            gt[u] = gate[he];
            cc[u] = (1.0f - gt[u]) * g * g;

            float lf    = (float)l0;
            float fl    = f[u] * lf;
            float resid = fmaf(f[u], lf, -fl);
            float frac  = (fl - floorf(fl)) + resid;
            float phk   = TWO_PI * frac;
            float argq  = phk + off[u];
            cq[u] = __cosf(argq); sq[u] = __sinf(argq);
            ck[u] = __cosf(phk);  sk[u] = __sinf(phk);
            float dph = TWO_PI * f[u];
            cF[u] = __cosf(dph);  sF[u] = __sinf(dph);
        }

        #pragma unroll
        for (int dl = 0; dl < 2; dl++) {
            int l = l0 + dl;
            size_t qi = ((size_t)(n * LL + l) * HH + h) * EE + e0;
            float2 qv2 = *(const float2*)(q + qi);
            float2 kv2 = *(const float2*)(k + qi);
            float qv[2] = { qv2.x * 0.125f, qv2.y * 0.125f };   // temp folded
            float kv[2] = { kv2.x, kv2.y };

            size_t base = ((size_t)nh * LL + l) * DD;
            // gate channel: one 4B store per array (dims e0, e0+1)
            *(uint32_t*)(g_Q + base + e0) = pack_h2(qv[0] * gt[0], qv[1] * gt[1]);
            *(uint32_t*)(g_K + base + e0) = pack_h2(kv[0], kv[1]);
            // cs channels: one 8B store per array (dims 64+2e0 .. 64+2e0+3)
            uint2 qcs, kcs;
            float qc0 = qv[0] * cc[0], qc1 = qv[1] * cc[1];
            qcs.x = pack_h2(qc0 * cq[0], qc0 * sq[0]);
            qcs.y = pack_h2(qc1 * cq[1], qc1 * sq[1]);
            kcs.x = pack_h2(kv[0] * ck[0], kv[0] * sk[0]);
            kcs.y = pack_h2(kv[1] * ck[1], kv[1] * sk[1]);
            *(uint2*)(g_Q + base + 64 + 2 * e0) = qcs;
            *(uint2*)(g_K + base + 64 + 2 * e0) = kcs;

            // rotate phases by 2*pi*f for next l
            #pragma unroll
            for (int u = 0; u < 2; u++) {
                float c2 = cq[u] * cF[u] - sq[u] * sF[u];
                float s2 = sq[u] * cF[u] + cq[u] * sF[u];
                cq[u] = c2; sq[u] = s2;
                float c3 = ck[u] * cF[u] - sk[u] * sF[u];
                float s3 = sk[u] * cF[u] + ck[u] * sF[u];
                ck[u] = c3; sk[u] = s3;
            }
        }
    } else {
        __shared__ float sm[64 * 65];
        int t = blockIdx.x - 48;
        int s0 = t * 64;

        #pragma unroll
        for (int i = 0; i < 16; i++) {
            int idx = threadIdx.x + i * 256;
            int r = idx >> 6, e = idx & 63;
            sm[e * 65 + r] = values[((size_t)(n * LL + s0 + r) * HH + h) * EE + e];
        }
        __syncthreads();

        #pragma unroll
        for (int i = 0; i < 8; i++) {
            int pid = threadIdx.x + i * 256;
            int e = pid >> 5, s2 = pid & 31;
            size_t o = ((size_t)nh * EE + e) * LL + s0 + 2 * s2;
            *(uint32_t*)(g_V + o) = pack_h2(sm[e * 65 + 2 * s2], sm[e * 65 + 2 * s2 + 1]);
        }
    }
}

// ---------------------------------------------------------------------------
// attn: persistent work-queue flash attention, uniform fp16 single-product.
// QK: 12 k16-chunks x 8 n = 96 MMA/tile. AV: 32 MMA/tile.
// cp.async pipelined exactly as the proven R8/R12/R16 structure.
// ---------------------------------------------------------------------------
__global__ __launch_bounds__(128)
void attn_kernel(const float* __restrict__ mask, const float* __restrict__ keylen,
                 float* __restrict__ out) {
    extern __shared__ __half smem[];
    __half* sK = smem;                                // [64][KSTR]
    __half* sV = smem + 64 * KSTR;                    // [2][64][VSTR]

    const int tid  = threadIdx.x;
    const int w    = tid >> 5;
    const int lane = tid & 31;
    const int g    = lane >> 2, t = lane & 3;

    const uint32_t bK = smem_u32(sK);
    const uint32_t bV = smem_u32(sV);

    unsigned item = blockIdx.x;
    while (item < NITEMS) {
        const int nh = (int)(item / NTILE);
        const int lt = (int)(item % NTILE);
        const int nb = nh >> 3, h = nh & 7;
        const int l0 = lt * BQ;
        const int row0 = l0 + w * 16 + g;

        const uint4* gKB = (const uint4*)(g_K + (size_t)nh * LL * DD);

        // issue cp.async group for tile it2 (K single buf, V buf vb)
        auto issue_tile = [&](int it2, int vb) {
            const uint4* gKt = gKB + (size_t)it2 * 64 * DD / 8;
            #pragma unroll
            for (int i = 0; i < 12; i++) {
                int idx = tid + i * 128;
                int r = idx / 24, c = idx % 24;
                uint32_t off = (uint32_t)(r * KSTR + c * 8) * 2u;
                CP16(bK + off, gKt + idx);
            }
            #pragma unroll
            for (int i = 0; i < 4; i++) {
                int idx = tid + i * 128;
                int r = idx / 8, c = idx % 8;
                size_t go = ((size_t)nh * EE + r) * LL + it2 * 64 + c * 8;
                uint32_t off = (uint32_t)(vb * 64 * VSTR + r * VSTR + c * 8) * 2u;
                CP16(bV + off, (const uint4*)(g_V + go));
            }
        };

        issue_tile(0, 0);
        CP_COMMIT();

        // ---- Q fragments (fp16; register resident for this item) ----
        uint32_t aQ[12][4];
        {
            const __half* qp = g_Q + ((size_t)nh * LL + row0) * DD;
            #pragma unroll
            for (int c = 0; c < 12; c++) {
                int d0 = c * 16 + 2 * t;
                aQ[c][0] = *(const uint32_t*)(qp + d0);
                aQ[c][1] = *(const uint32_t*)(qp + 8 * DD + d0);
                aQ[c][2] = *(const uint32_t*)(qp + d0 + 8);
                aQ[c][3] = *(const uint32_t*)(qp + 8 * DD + d0 + 8);
            }
        }

        float O[8][4];
        #pragma unroll
        for (int n = 0; n < 8; n++)
            #pragma unroll
            for (int j = 0; j < 4; j++) O[n][j] = 0.f;
        float m0 = -CUDART_INF_F, m1 = -CUDART_INF_F, ls0 = 0.f, ls1 = 0.f;

        const float* mrow0b = mask + (size_t)row0 * LL;
        const float* mrow1b = mrow0b + 8 * LL;
        const float* klb    = keylen + (size_t)nb * LL;

        for (int it = 0; it < NTILE; it++) {
            CP_WAIT0();
            __syncthreads();

            // ---- S = Q' K'^T : c outer, staged B frags, single f16 product ----
            float S[8][4];
            #pragma unroll
            for (int n = 0; n < 8; n++)
                #pragma unroll
                for (int j = 0; j < 4; j++) S[n][j] = 0.f;

            #pragma unroll
            for (int c = 0; c < 12; c++) {
                uint32_t bh[8][2];
                #pragma unroll
                for (int n = 0; n < 8; n++) {
                    const __half* kp = sK + (n * 8 + g) * KSTR + 2 * t + c * 16;
                    bh[n][0] = *(const uint32_t*)(kp);
                    bh[n][1] = *(const uint32_t*)(kp + 8);
                }
                #pragma unroll
                for (int n = 0; n < 8; n++) mma_f16(S[n], aQ[c], bh[n][0], bh[n][1]);
            }
            __syncthreads();   // all warps done reading K smem

            if (it + 1 < NTILE) issue_tile(it + 1, (it + 1) & 1);
            CP_COMMIT();

            // ---- bias: 0.125 * (mask + keylen) ----
            {
                const float* mr0 = mrow0b + it * 64;
                const float* mr1 = mrow1b + it * 64;
                const float* kl  = klb + it * 64;
                #pragma unroll
                for (int n = 0; n < 8; n++) {
                    int sc = n * 8 + 2 * t;
                    float2 a0 = *(const float2*)(mr0 + sc);
                    float2 a1 = *(const float2*)(mr1 + sc);
                    float2 kk = *(const float2*)(kl + sc);
                    S[n][0] += 0.125f * (a0.x + kk.x);
                    S[n][1] += 0.125f * (a0.y + kk.y);
                    S[n][2] += 0.125f * (a1.x + kk.x);
                    S[n][3] += 0.125f * (a1.y + kk.y);
                }
            }

            // ---- online softmax (rows quad-local) ----
            float mx0 = S[0][0], mx1 = S[0][2];
            #pragma unroll
            for (int n = 0; n < 8; n++) {
                mx0 = fmaxf(mx0, fmaxf(S[n][0], S[n][1]));
                mx1 = fmaxf(mx1, fmaxf(S[n][2], S[n][3]));
            }
            mx0 = fmaxf(mx0, __shfl_xor_sync(0xffffffffu, mx0, 1));
            mx0 = fmaxf(mx0, __shfl_xor_sync(0xffffffffu, mx0, 2));
            mx1 = fmaxf(mx1, __shfl_xor_sync(0xffffffffu, mx1, 1));
            mx1 = fmaxf(mx1, __shfl_xor_sync(0xffffffffu, mx1, 2));
            float m0n = fmaxf(m0, mx0), m1n = fmaxf(m1, mx1);
            float c0 = __expf(m0 - m0n), c1 = __expf(m1 - m1n);
            m0 = m0n; m1 = m1n;
            float s0 = 0.f, s1 = 0.f;
            #pragma unroll
            for (int n = 0; n < 8; n++) {
                S[n][0] = __expf(S[n][0] - m0n);
                S[n][1] = __expf(S[n][1] - m0n);
                S[n][2] = __expf(S[n][2] - m1n);
                S[n][3] = __expf(S[n][3] - m1n);
                s0 += S[n][0] + S[n][1];
                s1 += S[n][2] + S[n][3];
                O[n][0] *= c0; O[n][1] *= c0;
                O[n][2] *= c1; O[n][3] *= c1;
            }
            s0 += __shfl_xor_sync(0xffffffffu, s0, 1);
            s0 += __shfl_xor_sync(0xffffffffu, s0, 2);
            s1 += __shfl_xor_sync(0xffffffffu, s1, 1);
            s1 += __shfl_xor_sync(0xffffffffu, s1, 2);
            ls0 = ls0 * c0 + s0;
            ls1 = ls1 * c1 + s1;

            // ---- P -> fp16 A-fragments (single product) ----
            uint32_t ph[4][4];
            #pragma unroll
            for (int kc = 0; kc < 4; kc++) {
                ph[kc][0] = pack_h2(S[2*kc][0],   S[2*kc][1]);
                ph[kc][1] = pack_h2(S[2*kc][2],   S[2*kc][3]);
                ph[kc][2] = pack_h2(S[2*kc+1][0], S[2*kc+1][1]);
                ph[kc][3] = pack_h2(S[2*kc+1][2], S[2*kc+1][3]);
            }

            // ---- O += P V : kc outer, staged V frags, single fp16 product ----
            const __half* vb = sV + (it & 1) * 64 * VSTR;
            #pragma unroll
            for (int kc = 0; kc < 4; kc++) {
                uint32_t vh[8][2];
                #pragma unroll
                for (int n = 0; n < 8; n++) {
                    const __half* vhp = vb + (n * 8 + g) * VSTR + 2 * t + kc * 16;
                    vh[n][0] = *(const uint32_t*)(vhp);
                    vh[n][1] = *(const uint32_t*)(vhp + 8);
                }
                #pragma unroll
                for (int n = 0; n < 8; n++) mma_f16(O[n], ph[kc], vh[n][0], vh[n][1]);
            }
        }

        // ---- epilogue for this item ----
        float inv0 = 1.0f / ls0, inv1 = 1.0f / ls1;
        float* o0 = out + ((size_t)(nb * LL + row0) * HH + h) * EE;
        float* o1 = o0 + 8 * HH * EE;
        #pragma unroll
        for (int n = 0; n < 8; n++) {
            int e = n * 8 + 2 * t;
            *(float2*)(o0 + e) = make_float2(O[n][0] * inv0, O[n][1] * inv0);
            *(float2*)(o1 + e) = make_float2(O[n][2] * inv1, O[n][3] * inv1);
        }

        // ---- next work item ----
        __shared__ unsigned s_item;
        __syncthreads();
        if (tid == 0) s_item = atomicAdd(&g_ctr, 1u);
        __syncthreads();
        item = s_item;
    }
}

// ---------------------------------------------------------------------------
extern "C" void kernel_launch(void* const* d_in, const int* in_sizes, int n_in,
                              void* d_out, int out_size) {
    const float* queries = (const float*)d_in[0];
    const float* keys    = (const float*)d_in[1];
    const float* values  = (const float*)d_in[2];
    const float* mask    = (const float*)d_in[3];
    const float* keylen  = (const float*)d_in[4];
    const float* freqs   = (const float*)d_in[5];
    const float* offsets = (const float*)d_in[6];
    const float* gains   = (const float*)d_in[7];
    const float* gate    = (const float*)d_in[8];
    float* out = (float*)d_out;

    prep_kernel<<<dim3(48 + NTILE, NH), 256>>>(queries, keys, values,
                                               freqs, offsets, gains, gate);

    const int smem = (64 * KSTR + 2 * 64 * VSTR) * 2;   // 44032 B
    cudaFuncSetAttribute(attn_kernel, cudaFuncAttributeMaxDynamicSharedMemorySize, smem);
    attn_kernel<<<GRID_ATTN, 128, smem>>>(mask, keylen, out);
}